// round 5
// baseline (speedup 1.0000x reference)
#include <cuda_runtime.h>
#include <math.h>

// Problem constants
#define CDIM   96
#define NTOK   64           // tokens per window (4*4*4)
#define NWIN   8192         // 2 batches * 16^3 windows
#define NH     3
#define HD     32
#define QKV_LD 289          // 288 + 1 pad (stride % 32 == 1 -> conflict-free)
#define S_LD   65           // 64 + 1 pad
#define TOKENS (2*64*64*64) // 524288

// Scratch for inter-block activations (201 MB). Static device global: allowed.
__device__ float g_scratch[(size_t)TOKENS * CDIM];

// Dynamic smem sizes (bytes)
#define ASMEM ((64*96 + 64*96 + 64*QKV_LD + 64*S_LD + 64*96 + 343*3) * 4)
#define MSMEM ((64*96 + 64*96 + 64*384) * 4)

// ---------------------------------------------------------------------------
// Fused: LN1 -> window partition (with shift) -> QKV -> attn(+rel bias)
//        -> softmax -> P@V -> proj -> +residual -> write (reverse shift)
// One CTA per window, 256 threads.
// ---------------------------------------------------------------------------
__global__ __launch_bounds__(256, 1) void attn_kernel(
    const float* __restrict__ x, float* __restrict__ out,
    const float* __restrict__ Wqkv, const float* __restrict__ Bqkv,
    const float* __restrict__ Wp,   const float* __restrict__ Bp,
    const float* __restrict__ tb,
    const float* __restrict__ g1,   const float* __restrict__ b1,
    int shift)
{
    extern __shared__ float sm[];
    float* xres = sm;                   // 64 x 96 (pre-LN residual)
    float* xw   = xres + 64*96;         // 64 x 96 (LN'd)
    float* qkv  = xw   + 64*96;         // 64 x QKV_LD
    float* S    = qkv  + 64*QKV_LD;     // 64 x S_LD
    float* ao   = S    + 64*S_LD;       // 64 x 96 (attn out, all heads)
    float* tbl  = ao   + 64*96;         // 343*3 rel-bias table

    const int tid  = threadIdx.x;
    const int lane = tid & 31;
    const int warp = tid >> 5;

    const int bw   = blockIdx.x;
    const int b    = bw >> 12;          // / 4096
    const int widx = bw & 4095;
    const int wd   = widx >> 8;
    const int wh   = (widx >> 4) & 15;
    const int ww   = widx & 15;

    for (int i = tid; i < 343*3; i += 256) tbl[i] = tb[i];

    // ---- load + LayerNorm1 (one warp per token, 96 ch = 3 per lane) ----
    for (int t = warp; t < 64; t += 8) {
        int td = t >> 4, th = (t >> 2) & 3, tw = t & 3;
        int gd = (wd*4 + td + shift) & 63;
        int gh = (wh*4 + th + shift) & 63;
        int gw = (ww*4 + tw + shift) & 63;
        const float* src = x + ((((b*64 + gd)*64 + gh)*64 + gw) * 96);
        float v0 = src[lane], v1 = src[lane+32], v2 = src[lane+64];
        float s  = v0+v1+v2;
        float sq = v0*v0 + v1*v1 + v2*v2;
        #pragma unroll
        for (int o = 16; o; o >>= 1) {
            s  += __shfl_xor_sync(0xffffffffu, s,  o);
            sq += __shfl_xor_sync(0xffffffffu, sq, o);
        }
        float mean = s * (1.0f/96.0f);
        float var  = sq * (1.0f/96.0f) - mean*mean;
        float rstd = rsqrtf(var + 1e-5f);
        xres[t*96+lane]    = v0;
        xres[t*96+lane+32] = v1;
        xres[t*96+lane+64] = v2;
        xw[t*96+lane]      = (v0-mean)*rstd*g1[lane]    + b1[lane];
        xw[t*96+lane+32]   = (v1-mean)*rstd*g1[lane+32] + b1[lane+32];
        xw[t*96+lane+64]   = (v2-mean)*rstd*g1[lane+64] + b1[lane+64];
    }
    __syncthreads();

    // ---- QKV GEMM: (64x96) @ (96x288) + bias; q pre-scaled by 1/sqrt(32) ----
    {
        float acc[8][9];
        #pragma unroll
        for (int j = 0; j < 9; j++) {
            float bb = Bqkv[lane + 32*j];
            #pragma unroll
            for (int i = 0; i < 8; i++) acc[i][j] = bb;
        }
        for (int k = 0; k < 96; k++) {
            float a[8];
            #pragma unroll
            for (int i = 0; i < 8; i++) a[i] = xw[(warp + 8*i)*96 + k];
            #pragma unroll
            for (int j = 0; j < 9; j++) {
                float w = Wqkv[k*288 + lane + 32*j];
                #pragma unroll
                for (int i = 0; i < 8; i++) acc[i][j] += a[i]*w;
            }
        }
        const float qs = 0.17677669529663687f;  // 32^-0.5
        #pragma unroll
        for (int j = 0; j < 9; j++) {
            int c = lane + 32*j;
            float scale = (c < 96) ? qs : 1.0f;
            #pragma unroll
            for (int i = 0; i < 8; i++)
                qkv[(warp + 8*i)*QKV_LD + c] = acc[i][j] * scale;
        }
    }
    __syncthreads();

    // ---- per-head attention ----
    for (int h = 0; h < NH; h++) {
        const int qoff = h*HD, koff = 96 + h*HD, voff = 192 + h*HD;

        // S = q @ k^T + bias   (thread: 8 q-rows x 2 k-cols)
        {
            float sacc[8][2];
            #pragma unroll
            for (int i = 0; i < 8; i++) { sacc[i][0] = 0.f; sacc[i][1] = 0.f; }
            for (int d = 0; d < HD; d++) {
                float kv0 = qkv[lane*QKV_LD + koff + d];
                float kv1 = qkv[(lane+32)*QKV_LD + koff + d];
                #pragma unroll
                for (int i = 0; i < 8; i++) {
                    float qv = qkv[(warp + 8*i)*QKV_LD + qoff + d];
                    sacc[i][0] += qv*kv0;
                    sacc[i][1] += qv*kv1;
                }
            }
            #pragma unroll
            for (int i = 0; i < 8; i++) {
                int q = warp + 8*i;
                int qd = q >> 4, qh = (q >> 2) & 3, qw = q & 3;
                #pragma unroll
                for (int j = 0; j < 2; j++) {
                    int kk = lane + 32*j;
                    int kd = kk >> 4, kh = (kk >> 2) & 3, kw = kk & 3;
                    int ridx = (qd-kd+3)*49 + (qh-kh+3)*7 + (qw-kw+3);
                    S[q*S_LD + kk] = sacc[i][j] + tbl[ridx*3 + h];
                }
            }
        }
        __syncthreads();

        // softmax (4 lanes per row, 16 cols each)
        {
            int row = tid >> 2, sub = tid & 3;
            float vals[16];
            float m = -1e30f;
            #pragma unroll
            for (int c = 0; c < 16; c++) {
                vals[c] = S[row*S_LD + sub*16 + c];
                m = fmaxf(m, vals[c]);
            }
            m = fmaxf(m, __shfl_xor_sync(0xffffffffu, m, 1));
            m = fmaxf(m, __shfl_xor_sync(0xffffffffu, m, 2));
            float sum = 0.f;
            #pragma unroll
            for (int c = 0; c < 16; c++) { vals[c] = expf(vals[c] - m); sum += vals[c]; }
            sum += __shfl_xor_sync(0xffffffffu, sum, 1);
            sum += __shfl_xor_sync(0xffffffffu, sum, 2);
            float inv = 1.0f / sum;
            #pragma unroll
            for (int c = 0; c < 16; c++) S[row*S_LD + sub*16 + c] = vals[c]*inv;
        }
        __syncthreads();

        // out = P @ v   (thread: 8 q-rows, d = lane)
        {
            float oacc[8];
            #pragma unroll
            for (int i = 0; i < 8; i++) oacc[i] = 0.f;
            for (int kk = 0; kk < 64; kk++) {
                float vv = qkv[kk*QKV_LD + voff + lane];
                #pragma unroll
                for (int i = 0; i < 8; i++)
                    oacc[i] += S[(warp + 8*i)*S_LD + kk] * vv;
            }
            #pragma unroll
            for (int i = 0; i < 8; i++)
                ao[(warp + 8*i)*96 + h*HD + lane] = oacc[i];
        }
        __syncthreads();
    }

    // ---- proj: (64x96) @ (96x96) + bias + residual -> global ----
    {
        float pacc[8][3];
        #pragma unroll
        for (int j = 0; j < 3; j++) {
            float bb = Bp[lane + 32*j];
            #pragma unroll
            for (int i = 0; i < 8; i++) pacc[i][j] = bb;
        }
        for (int k = 0; k < 96; k++) {
            float a[8];
            #pragma unroll
            for (int i = 0; i < 8; i++) a[i] = ao[(warp + 8*i)*96 + k];
            #pragma unroll
            for (int j = 0; j < 3; j++) {
                float w = Wp[k*96 + lane + 32*j];
                #pragma unroll
                for (int i = 0; i < 8; i++) pacc[i][j] += a[i]*w;
            }
        }
        #pragma unroll
        for (int i = 0; i < 8; i++) {
            int t = warp + 8*i;
            int td = t >> 4, th = (t >> 2) & 3, tw = t & 3;
            int gd = (wd*4 + td + shift) & 63;
            int gh = (wh*4 + th + shift) & 63;
            int gw = (ww*4 + tw + shift) & 63;
            float* dst = out + ((((b*64 + gd)*64 + gh)*64 + gw) * 96);
            #pragma unroll
            for (int j = 0; j < 3; j++) {
                int c = lane + 32*j;
                dst[c] = pacc[i][j] + xres[t*96 + c];
            }
        }
    }
}

// ---------------------------------------------------------------------------
// Fused: LN2 -> MLP (96->384 GELU ->96) -> +residual, in-place.
// One CTA per 64 tokens, 256 threads.
// ---------------------------------------------------------------------------
__global__ __launch_bounds__(256, 1) void mlp_kernel(
    float* __restrict__ xa,
    const float* __restrict__ g2, const float* __restrict__ b2,
    const float* __restrict__ W1, const float* __restrict__ B1,
    const float* __restrict__ W2, const float* __restrict__ B2)
{
    extern __shared__ float sm[];
    float* y  = sm;            // 64 x 96 (LN'd)
    float* xr = y  + 64*96;    // 64 x 96 (residual)
    float* hb = xr + 64*96;    // 64 x 384 (hidden after GELU)

    const int tid  = threadIdx.x;
    const int lane = tid & 31;
    const int warp = tid >> 5;
    const int base = blockIdx.x * 64;

    // ---- load + LayerNorm2 ----
    for (int t = warp; t < 64; t += 8) {
        const float* src = xa + (size_t)(base + t) * 96;
        float v0 = src[lane], v1 = src[lane+32], v2 = src[lane+64];
        float s  = v0+v1+v2;
        float sq = v0*v0 + v1*v1 + v2*v2;
        #pragma unroll
        for (int o = 16; o; o >>= 1) {
            s  += __shfl_xor_sync(0xffffffffu, s,  o);
            sq += __shfl_xor_sync(0xffffffffu, sq, o);
        }
        float mean = s * (1.0f/96.0f);
        float var  = sq * (1.0f/96.0f) - mean*mean;
        float rstd = rsqrtf(var + 1e-5f);
        xr[t*96+lane]    = v0;
        xr[t*96+lane+32] = v1;
        xr[t*96+lane+64] = v2;
        y[t*96+lane]     = (v0-mean)*rstd*g2[lane]    + b2[lane];
        y[t*96+lane+32]  = (v1-mean)*rstd*g2[lane+32] + b2[lane+32];
        y[t*96+lane+64]  = (v2-mean)*rstd*g2[lane+64] + b2[lane+64];
    }
    __syncthreads();

    // ---- GEMM1: (64x96) @ (96x384) + b1, exact GELU ----
    {
        float acc[8][12];
        #pragma unroll
        for (int j = 0; j < 12; j++) {
            float bb = B1[lane + 32*j];
            #pragma unroll
            for (int i = 0; i < 8; i++) acc[i][j] = bb;
        }
        for (int k = 0; k < 96; k++) {
            float a[8];
            #pragma unroll
            for (int i = 0; i < 8; i++) a[i] = y[(warp + 8*i)*96 + k];
            #pragma unroll
            for (int j = 0; j < 12; j++) {
                float w = W1[k*384 + lane + 32*j];
                #pragma unroll
                for (int i = 0; i < 8; i++) acc[i][j] += a[i]*w;
            }
        }
        #pragma unroll
        for (int j = 0; j < 12; j++) {
            int c = lane + 32*j;
            #pragma unroll
            for (int i = 0; i < 8; i++) {
                float u = acc[i][j];
                float g = 0.5f * u * (1.0f + erff(u * 0.70710678118654752f));
                hb[(warp + 8*i)*384 + c] = g;
            }
        }
    }
    __syncthreads();

    // ---- GEMM2: (64x384) @ (384x96) + b2 + residual -> global (in-place) ----
    {
        float acc[8][3];
        #pragma unroll
        for (int j = 0; j < 3; j++) {
            float bb = B2[lane + 32*j];
            #pragma unroll
            for (int i = 0; i < 8; i++) acc[i][j] = bb;
        }
        for (int k = 0; k < 384; k++) {
            float a[8];
            #pragma unroll
            for (int i = 0; i < 8; i++) a[i] = hb[(warp + 8*i)*384 + k];
            #pragma unroll
            for (int j = 0; j < 3; j++) {
                float w = W2[k*96 + lane + 32*j];
                #pragma unroll
                for (int i = 0; i < 8; i++) acc[i][j] += a[i]*w;
            }
        }
        #pragma unroll
        for (int i = 0; i < 8; i++) {
            int t = warp + 8*i;
            float* dst = xa + (size_t)(base + t) * 96;
            #pragma unroll
            for (int j = 0; j < 3; j++) {
                int c = lane + 32*j;
                dst[c] = acc[i][j] + xr[t*96 + c];
            }
        }
    }
}

// ---------------------------------------------------------------------------
extern "C" void kernel_launch(void* const* d_in, const int* in_sizes, int n_in,
                              void* d_out, int out_size)
{
    const float* x      = (const float*)d_in[0];
    const float* qkv_w  = (const float*)d_in[1];
    const float* qkv_b  = (const float*)d_in[2];
    const float* proj_w = (const float*)d_in[3];
    const float* proj_b = (const float*)d_in[4];
    const float* btab   = (const float*)d_in[5];
    const float* ln1g   = (const float*)d_in[6];
    const float* ln1b   = (const float*)d_in[7];
    const float* ln2g   = (const float*)d_in[8];
    const float* ln2b   = (const float*)d_in[9];
    const float* w1     = (const float*)d_in[10];
    const float* b1     = (const float*)d_in[11];
    const float* w2     = (const float*)d_in[12];
    const float* b2     = (const float*)d_in[13];
    float* out = (float*)d_out;

    float* scratch = nullptr;
    cudaGetSymbolAddress((void**)&scratch, g_scratch);

    cudaFuncSetAttribute(attn_kernel, cudaFuncAttributeMaxDynamicSharedMemorySize, ASMEM);
    cudaFuncSetAttribute(mlp_kernel,  cudaFuncAttributeMaxDynamicSharedMemorySize, MSMEM);

    // ---- block 0 (shift 0) ----
    attn_kernel<<<NWIN, 256, ASMEM>>>(x, scratch,
        qkv_w, qkv_b, proj_w, proj_b, btab, ln1g, ln1b, 0);
    mlp_kernel<<<TOKENS/64, 256, MSMEM>>>(scratch,
        ln2g, ln2b, w1, b1, w2, b2);

    // ---- block 1 (shift 2), per-block parameter offsets ----
    attn_kernel<<<NWIN, 256, ASMEM>>>(scratch, out,
        qkv_w + 96*288, qkv_b + 288, proj_w + 96*96, proj_b + 96,
        btab + 343*3, ln1g + 96, ln1b + 96, 2);
    mlp_kernel<<<TOKENS/64, 256, MSMEM>>>(out,
        ln2g + 96, ln2b + 96, w1 + 96*384, b1 + 384, w2 + 384*96, b2 + 96);
}

// round 6
// speedup vs baseline: 1.5617x; 1.5617x over previous
#include <cuda_runtime.h>
#include <math.h>

typedef unsigned long long u64;

#define CDIM   96
#define NWIN   8192
#define TOKENS (2*64*64*64)
#define QKV_LD 292          // %32==4 -> conflict-free float4 column reads, 16B aligned rows
#define S_LD   68           // %32==4, 16B aligned rows

// Static device scratch (no allocs allowed)
__device__ float g_scratch[(size_t)TOKENS * CDIM];   // inter-block activations
__device__ u64   g_w2pk[2 * 192 * 96];               // k-pair-packed W2, both layers

#define ASMEM ((64*96 + 64*QKV_LD + 3*64*S_LD + 1032) * 4)
#define MSMEM ((64*96 + 64*384) * 4)

// ---- packed fp32x2 helpers (Blackwell FFMA2 path) ----
__device__ __forceinline__ u64 pk2(float x, float y) {
    u64 r; asm("mov.b64 %0,{%1,%2};" : "=l"(r) : "f"(x), "f"(y)); return r;
}
__device__ __forceinline__ void upk2(float& x, float& y, u64 v) {
    asm("mov.b64 {%0,%1},%2;" : "=f"(x), "=f"(y) : "l"(v));
}
__device__ __forceinline__ void fma2(u64& d, u64 a, u64 b) {
    asm("fma.rn.f32x2 %0,%1,%2,%0;" : "+l"(d) : "l"(a), "l"(b));
}

// ---------------------------------------------------------------------------
// Prep: interleave W2 (both layers) into k-pair u64s: g_w2pk[L][k2*96+c] =
// {W2[2k2][c], W2[2k2+1][c]}
// ---------------------------------------------------------------------------
__global__ void pack_w2_kernel(const float* __restrict__ w2) {
    int idx = blockIdx.x * blockDim.x + threadIdx.x;
    if (idx >= 2 * 192 * 96) return;
    int layer = idx / (192 * 96);
    int r  = idx % (192 * 96);
    int k2 = r / 96, c = r % 96;
    const float* w = w2 + (size_t)layer * 384 * 96;
    g_w2pk[idx] = pk2(w[(2*k2) * 96 + c], w[(2*k2 + 1) * 96 + c]);
}

// ---------------------------------------------------------------------------
// Attention block: LN1 -> QKV -> S(+bias) all heads -> softmax -> P@V -> proj
// -> +residual. One CTA per 4x4x4 window, 512 threads, shift folded in.
// ---------------------------------------------------------------------------
__global__ __launch_bounds__(512, 1) void attn_kernel(
    const float* __restrict__ x, float* __restrict__ out,
    const float* __restrict__ Wqkv, const float* __restrict__ Bqkv,
    const float* __restrict__ Wp,   const float* __restrict__ Bp,
    const float* __restrict__ tb,
    const float* __restrict__ g1,   const float* __restrict__ b1,
    int shift)
{
    extern __shared__ float sm[];
    float* xw  = sm;                    // 64x96 LN'd (aliased as ao after QKV)
    float* qkv = xw + 64*96;            // 64 x 292
    float* S3  = qkv + 64*QKV_LD;       // 3 x 64 x 68
    float* tbl = S3 + 3*64*S_LD;        // 1029 (+3 pad)
    float* ao  = xw;

    const int tid  = threadIdx.x;
    const int lane = tid & 31;
    const int warp = tid >> 5;

    const int bw   = blockIdx.x;
    const int b    = bw >> 12;
    const int widx = bw & 4095;
    const int wd   = widx >> 8;
    const int wh   = (widx >> 4) & 15;
    const int ww   = widx & 15;

    for (int i = tid; i < 1029; i += 512) tbl[i] = tb[i];

    // ---- LN1 (one warp per token) ----
    for (int t = warp; t < 64; t += 16) {
        int td = t >> 4, th = (t >> 2) & 3, tw = t & 3;
        int gd = (wd*4 + td + shift) & 63;
        int gh = (wh*4 + th + shift) & 63;
        int gw = (ww*4 + tw + shift) & 63;
        const float* src = x + (size_t)((((b*64 + gd)*64 + gh)*64 + gw)) * 96;
        float v0 = src[lane], v1 = src[lane+32], v2 = src[lane+64];
        float s  = v0 + v1 + v2;
        float sq = v0*v0 + v1*v1 + v2*v2;
        #pragma unroll
        for (int o = 16; o; o >>= 1) {
            s  += __shfl_xor_sync(0xffffffffu, s,  o);
            sq += __shfl_xor_sync(0xffffffffu, sq, o);
        }
        float mean = s * (1.0f/96.0f);
        float var  = sq * (1.0f/96.0f) - mean*mean;
        float rstd = rsqrtf(var + 1e-5f);
        xw[t*96+lane]    = (v0-mean)*rstd*g1[lane]    + b1[lane];
        xw[t*96+lane+32] = (v1-mean)*rstd*g1[lane+32] + b1[lane+32];
        xw[t*96+lane+64] = (v2-mean)*rstd*g1[lane+64] + b1[lane+64];
    }
    __syncthreads();

    // ---- QKV GEMM (FFMA2, col-pairs): rows warp+16i, cols 2*lane+64jj(+1), 256+lane ----
    {
        u64 acc2[4][4];
        float acc8[4];
        #pragma unroll
        for (int jj = 0; jj < 4; jj++) {
            u64 bb = *(const u64*)&Bqkv[2*lane + 64*jj];
            #pragma unroll
            for (int i = 0; i < 4; i++) acc2[i][jj] = bb;
        }
        {
            float b8 = Bqkv[256 + lane];
            #pragma unroll
            for (int i = 0; i < 4; i++) acc8[i] = b8;
        }
        for (int k4 = 0; k4 < 24; k4++) {
            float a[4][4];
            #pragma unroll
            for (int i = 0; i < 4; i++) {
                float4 v = *(const float4*)&xw[(warp + 16*i)*96 + 4*k4];
                a[i][0]=v.x; a[i][1]=v.y; a[i][2]=v.z; a[i][3]=v.w;
            }
            #pragma unroll
            for (int kk = 0; kk < 4; kk++) {
                int k = 4*k4 + kk;
                u64 ap[4];
                #pragma unroll
                for (int i = 0; i < 4; i++) ap[i] = pk2(a[i][kk], a[i][kk]);
                #pragma unroll
                for (int jj = 0; jj < 4; jj++) {
                    u64 w = *(const u64*)&Wqkv[k*288 + 2*lane + 64*jj];
                    #pragma unroll
                    for (int i = 0; i < 4; i++) fma2(acc2[i][jj], ap[i], w);
                }
                float w8 = Wqkv[k*288 + 256 + lane];
                #pragma unroll
                for (int i = 0; i < 4; i++) acc8[i] += a[i][kk]*w8;
            }
        }
        const float qs = 0.17677669529663687f;  // 32^-0.5
        #pragma unroll
        for (int jj = 0; jj < 4; jj++) {
            int c0 = 2*lane + 64*jj;
            float s0 = (c0   < 96) ? qs : 1.0f;
            float s1 = (c0+1 < 96) ? qs : 1.0f;
            #pragma unroll
            for (int i = 0; i < 4; i++) {
                float vx, vy; upk2(vx, vy, acc2[i][jj]);
                *(float2*)&qkv[(warp + 16*i)*QKV_LD + c0] = make_float2(vx*s0, vy*s1);
            }
        }
        #pragma unroll
        for (int i = 0; i < 4; i++)
            qkv[(warp + 16*i)*QKV_LD + 256 + lane] = acc8[i];
    }
    __syncthreads();

    // ---- S = qK^T + bias, all heads (FFMA2 over d-pairs) ----
    #pragma unroll
    for (int h = 0; h < 3; h++) {
        u64 sacc[4][2];
        #pragma unroll
        for (int i = 0; i < 4; i++) { sacc[i][0] = 0ULL; sacc[i][1] = 0ULL; }
        const float* kp0 = &qkv[lane*QKV_LD      + 96 + h*32];
        const float* kp1 = &qkv[(lane+32)*QKV_LD + 96 + h*32];
        #pragma unroll
        for (int d4 = 0; d4 < 8; d4++) {
            ulonglong2 k0 = *(const ulonglong2*)&kp0[4*d4];
            ulonglong2 k1 = *(const ulonglong2*)&kp1[4*d4];
            #pragma unroll
            for (int i = 0; i < 4; i++) {
                ulonglong2 qv = *(const ulonglong2*)&qkv[(warp + 16*i)*QKV_LD + h*32 + 4*d4];
                fma2(sacc[i][0], qv.x, k0.x);
                fma2(sacc[i][0], qv.y, k0.y);
                fma2(sacc[i][1], qv.x, k1.x);
                fma2(sacc[i][1], qv.y, k1.y);
            }
        }
        #pragma unroll
        for (int i = 0; i < 4; i++) {
            int q = warp + 16*i;
            int qd = q >> 4, qh = (q >> 2) & 3, qw = q & 3;
            #pragma unroll
            for (int j = 0; j < 2; j++) {
                int kk = lane + 32*j;
                int kd = kk >> 4, kh = (kk >> 2) & 3, kw = kk & 3;
                int ridx = (qd-kd+3)*49 + (qh-kh+3)*7 + (qw-kw+3);
                float lo, hi; upk2(lo, hi, sacc[i][j]);
                S3[(h*64 + q)*S_LD + kk] = lo + hi + tbl[ridx*3 + h];
            }
        }
    }
    __syncthreads();

    // ---- softmax: 8 lanes per row, all heads ----
    {
        int row = tid >> 3, sub = tid & 7;
        #pragma unroll
        for (int h = 0; h < 3; h++) {
            float* Sr = &S3[(h*64 + row)*S_LD + sub*8];
            float4 v0 = *(float4*)Sr;
            float4 v1 = *(float4*)(Sr + 4);
            float vals[8] = {v0.x,v0.y,v0.z,v0.w, v1.x,v1.y,v1.z,v1.w};
            float m = vals[0];
            #pragma unroll
            for (int c = 1; c < 8; c++) m = fmaxf(m, vals[c]);
            m = fmaxf(m, __shfl_xor_sync(0xffffffffu, m, 1));
            m = fmaxf(m, __shfl_xor_sync(0xffffffffu, m, 2));
            m = fmaxf(m, __shfl_xor_sync(0xffffffffu, m, 4));
            float ssum = 0.f;
            #pragma unroll
            for (int c = 0; c < 8; c++) { vals[c] = __expf(vals[c] - m); ssum += vals[c]; }
            ssum += __shfl_xor_sync(0xffffffffu, ssum, 1);
            ssum += __shfl_xor_sync(0xffffffffu, ssum, 2);
            ssum += __shfl_xor_sync(0xffffffffu, ssum, 4);
            float inv = 1.0f / ssum;
            *(float4*)Sr       = make_float4(vals[0]*inv, vals[1]*inv, vals[2]*inv, vals[3]*inv);
            *(float4*)(Sr + 4) = make_float4(vals[4]*inv, vals[5]*inv, vals[6]*inv, vals[7]*inv);
        }
    }
    __syncthreads();

    // ---- P@V, all heads (FFMA2 over k-pairs); out col = h*32+lane ----
    {
        u64 oacc[4][3];
        #pragma unroll
        for (int i = 0; i < 4; i++)
            #pragma unroll
            for (int h = 0; h < 3; h++) oacc[i][h] = 0ULL;
        for (int k4 = 0; k4 < 16; k4++) {
            #pragma unroll
            for (int h = 0; h < 3; h++) {
                float v0 = qkv[(4*k4+0)*QKV_LD + 192 + h*32 + lane];
                float v1 = qkv[(4*k4+1)*QKV_LD + 192 + h*32 + lane];
                float v2 = qkv[(4*k4+2)*QKV_LD + 192 + h*32 + lane];
                float v3 = qkv[(4*k4+3)*QKV_LD + 192 + h*32 + lane];
                u64 vp0 = pk2(v0, v1), vp1 = pk2(v2, v3);
                #pragma unroll
                for (int i = 0; i < 4; i++) {
                    ulonglong2 s = *(const ulonglong2*)&S3[(h*64 + warp + 16*i)*S_LD + 4*k4];
                    fma2(oacc[i][h], s.x, vp0);
                    fma2(oacc[i][h], s.y, vp1);
                }
            }
        }
        #pragma unroll
        for (int i = 0; i < 4; i++)
            #pragma unroll
            for (int h = 0; h < 3; h++) {
                float lo, hi; upk2(lo, hi, oacc[i][h]);
                ao[(warp + 16*i)*96 + h*32 + lane] = lo + hi;
            }
    }
    __syncthreads();

    // ---- proj + residual (residual re-read from x) ----
    {
        float pacc[4][3];
        float2 bb = *(const float2*)&Bp[2*lane];
        float  b3 = Bp[64 + lane];
        #pragma unroll
        for (int i = 0; i < 4; i++) { pacc[i][0] = bb.x; pacc[i][1] = bb.y; pacc[i][2] = b3; }
        for (int k4 = 0; k4 < 24; k4++) {
            float a[4][4];
            #pragma unroll
            for (int i = 0; i < 4; i++) {
                float4 v = *(const float4*)&ao[(warp + 16*i)*96 + 4*k4];
                a[i][0]=v.x; a[i][1]=v.y; a[i][2]=v.z; a[i][3]=v.w;
            }
            #pragma unroll
            for (int kk = 0; kk < 4; kk++) {
                int k = 4*k4 + kk;
                float2 w  = *(const float2*)&Wp[k*96 + 2*lane];
                float  w3 = Wp[k*96 + 64 + lane];
                #pragma unroll
                for (int i = 0; i < 4; i++) {
                    pacc[i][0] += a[i][kk]*w.x;
                    pacc[i][1] += a[i][kk]*w.y;
                    pacc[i][2] += a[i][kk]*w3;
                }
            }
        }
        #pragma unroll
        for (int i = 0; i < 4; i++) {
            int t = warp + 16*i;
            int td = t >> 4, th = (t >> 2) & 3, tw = t & 3;
            int gd = (wd*4 + td + shift) & 63;
            int gh = (wh*4 + th + shift) & 63;
            int gw = (ww*4 + tw + shift) & 63;
            size_t idx = (size_t)((((b*64 + gd)*64 + gh)*64 + gw)) * 96;
            const float* rx = x + idx;
            float* dst = out + idx;
            dst[2*lane]   = pacc[i][0] + rx[2*lane];
            dst[2*lane+1] = pacc[i][1] + rx[2*lane+1];
            dst[64+lane]  = pacc[i][2] + rx[64+lane];
        }
    }
}

// ---------------------------------------------------------------------------
// MLP block: LN2 -> GEMM1(96->384, FFMA2 col-pairs) -> exact GELU ->
// GEMM2(384->96, FFMA2 k-pairs with prepacked W2) -> +residual, in-place.
// One CTA per 64 tokens, 512 threads.
// ---------------------------------------------------------------------------
__global__ __launch_bounds__(512, 1) void mlp_kernel(
    float* __restrict__ xa,
    const float* __restrict__ g2, const float* __restrict__ b2,
    const float* __restrict__ W1, const float* __restrict__ B1,
    const u64*  __restrict__ W2p, const float* __restrict__ B2)
{
    extern __shared__ float sm[];
    float* y  = sm;           // 64 x 96 (LN'd)
    float* hb = y + 64*96;    // 64 x 384 (hidden after GELU)

    const int tid  = threadIdx.x;
    const int lane = tid & 31;
    const int warp = tid >> 5;
    const size_t base = (size_t)blockIdx.x * 64;

    // ---- LN2 ----
    for (int t = warp; t < 64; t += 16) {
        const float* src = xa + (base + t) * 96;
        float v0 = src[lane], v1 = src[lane+32], v2 = src[lane+64];
        float s  = v0 + v1 + v2;
        float sq = v0*v0 + v1*v1 + v2*v2;
        #pragma unroll
        for (int o = 16; o; o >>= 1) {
            s  += __shfl_xor_sync(0xffffffffu, s,  o);
            sq += __shfl_xor_sync(0xffffffffu, sq, o);
        }
        float mean = s * (1.0f/96.0f);
        float var  = sq * (1.0f/96.0f) - mean*mean;
        float rstd = rsqrtf(var + 1e-5f);
        y[t*96+lane]    = (v0-mean)*rstd*g2[lane]    + b2[lane];
        y[t*96+lane+32] = (v1-mean)*rstd*g2[lane+32] + b2[lane+32];
        y[t*96+lane+64] = (v2-mean)*rstd*g2[lane+64] + b2[lane+64];
    }
    __syncthreads();

    // ---- GEMM1 (FFMA2 col-pairs): rows warp+16i, cols 4*lane+128jj..+3 ----
    {
        u64 acc2[4][6];
        #pragma unroll
        for (int jj = 0; jj < 3; jj++) {
            ulonglong2 bb = *(const ulonglong2*)&B1[4*lane + 128*jj];
            #pragma unroll
            for (int i = 0; i < 4; i++) { acc2[i][2*jj] = bb.x; acc2[i][2*jj+1] = bb.y; }
        }
        for (int k4 = 0; k4 < 24; k4++) {
            float a[4][4];
            #pragma unroll
            for (int i = 0; i < 4; i++) {
                float4 v = *(const float4*)&y[(warp + 16*i)*96 + 4*k4];
                a[i][0]=v.x; a[i][1]=v.y; a[i][2]=v.z; a[i][3]=v.w;
            }
            #pragma unroll
            for (int kk = 0; kk < 4; kk++) {
                int k = 4*k4 + kk;
                u64 ap[4];
                #pragma unroll
                for (int i = 0; i < 4; i++) ap[i] = pk2(a[i][kk], a[i][kk]);
                #pragma unroll
                for (int jj = 0; jj < 3; jj++) {
                    ulonglong2 w = *(const ulonglong2*)&W1[k*384 + 4*lane + 128*jj];
                    #pragma unroll
                    for (int i = 0; i < 4; i++) {
                        fma2(acc2[i][2*jj],   ap[i], w.x);
                        fma2(acc2[i][2*jj+1], ap[i], w.y);
                    }
                }
            }
        }
        // exact GELU + store
        #pragma unroll
        for (int i = 0; i < 4; i++) {
            #pragma unroll
            for (int jj = 0; jj < 3; jj++) {
                float u0,u1,u2,u3;
                upk2(u0, u1, acc2[i][2*jj]);
                upk2(u2, u3, acc2[i][2*jj+1]);
                float g0 = 0.5f*u0*(1.0f + erff(u0*0.70710678118654752f));
                float g1v= 0.5f*u1*(1.0f + erff(u1*0.70710678118654752f));
                float g2v= 0.5f*u2*(1.0f + erff(u2*0.70710678118654752f));
                float g3 = 0.5f*u3*(1.0f + erff(u3*0.70710678118654752f));
                *(float4*)&hb[(warp + 16*i)*384 + 4*lane + 128*jj] = make_float4(g0,g1v,g2v,g3);
            }
        }
    }
    __syncthreads();

    // ---- GEMM2 (FFMA2 k-pairs, prepacked W2): cols 2*lane(+1), 64+lane ----
    {
        u64 acc2[4][3];
        #pragma unroll
        for (int i = 0; i < 4; i++) { acc2[i][0]=0ULL; acc2[i][1]=0ULL; acc2[i][2]=0ULL; }
        for (int k2 = 0; k2 < 192; k2++) {
            u64 a2[4];
            #pragma unroll
            for (int i = 0; i < 4; i++)
                a2[i] = *(const u64*)&hb[(warp + 16*i)*384 + 2*k2];
            u64 w0 = W2p[k2*96 + 2*lane];
            u64 w1 = W2p[k2*96 + 2*lane + 1];
            u64 w2 = W2p[k2*96 + 64 + lane];
            #pragma unroll
            for (int i = 0; i < 4; i++) {
                fma2(acc2[i][0], a2[i], w0);
                fma2(acc2[i][1], a2[i], w1);
                fma2(acc2[i][2], a2[i], w2);
            }
        }
        float2 bb = *(const float2*)&B2[2*lane];
        float  b3 = B2[64 + lane];
        #pragma unroll
        for (int i = 0; i < 4; i++) {
            float* p = xa + (base + warp + 16*i) * 96;
            float l0,h0,l1,h1,l2,h2;
            upk2(l0, h0, acc2[i][0]);
            upk2(l1, h1, acc2[i][1]);
            upk2(l2, h2, acc2[i][2]);
            float r0 = p[2*lane], r1 = p[2*lane+1], r2 = p[64+lane];
            p[2*lane]   = l0 + h0 + bb.x + r0;
            p[2*lane+1] = l1 + h1 + bb.y + r1;
            p[64+lane]  = l2 + h2 + b3   + r2;
        }
    }
}

// ---------------------------------------------------------------------------
extern "C" void kernel_launch(void* const* d_in, const int* in_sizes, int n_in,
                              void* d_out, int out_size)
{
    const float* x      = (const float*)d_in[0];
    const float* qkv_w  = (const float*)d_in[1];
    const float* qkv_b  = (const float*)d_in[2];
    const float* proj_w = (const float*)d_in[3];
    const float* proj_b = (const float*)d_in[4];
    const float* btab   = (const float*)d_in[5];
    const float* ln1g   = (const float*)d_in[6];
    const float* ln1b   = (const float*)d_in[7];
    const float* ln2g   = (const float*)d_in[8];
    const float* ln2b   = (const float*)d_in[9];
    const float* w1     = (const float*)d_in[10];
    const float* b1     = (const float*)d_in[11];
    const float* w2     = (const float*)d_in[12];
    const float* b2     = (const float*)d_in[13];
    float* out = (float*)d_out;

    float* scratch = nullptr;
    u64*   w2pk    = nullptr;
    cudaGetSymbolAddress((void**)&scratch, g_scratch);
    cudaGetSymbolAddress((void**)&w2pk,    g_w2pk);

    cudaFuncSetAttribute(attn_kernel, cudaFuncAttributeMaxDynamicSharedMemorySize, ASMEM);
    cudaFuncSetAttribute(mlp_kernel,  cudaFuncAttributeMaxDynamicSharedMemorySize, MSMEM);

    // Pre-pack W2 for both layers (k-pair interleave)
    pack_w2_kernel<<<(2*192*96 + 255)/256, 256>>>(w2);

    // ---- block 0 (shift 0) ----
    attn_kernel<<<NWIN, 512, ASMEM>>>(x, scratch,
        qkv_w, qkv_b, proj_w, proj_b, btab, ln1g, ln1b, 0);
    mlp_kernel<<<TOKENS/64, 512, MSMEM>>>(scratch,
        ln2g, ln2b, w1, b1, w2pk, b2);

    // ---- block 1 (shift 2) ----
    attn_kernel<<<NWIN, 512, ASMEM>>>(scratch, out,
        qkv_w + 96*288, qkv_b + 288, proj_w + 96*96, proj_b + 96,
        btab + 343*3, ln1g + 96, ln1b + 96, 2);
    mlp_kernel<<<TOKENS/64, 512, MSMEM>>>(out,
        ln2g + 96, ln2b + 96, w1 + 96*384, b1 + 384, w2pk + 192*96, b2 + 96);
}

// round 7
// speedup vs baseline: 2.8220x; 1.8070x over previous
#include <cuda_runtime.h>
#include <math.h>

typedef unsigned long long u64;
typedef unsigned int u32;

#define CDIM   96
#define NWIN   8192
#define TOKENS (2*64*64*64)
#define QKV_LD 292          // %32==4, 16B-aligned rows
#define S_LD   68
#define XW_LD  100          // %32==4 -> conflict-free mma A-fragment LDS
#define HB_LD  388          // %32==4

// Static device scratch (no allocs allowed)
__device__ float g_scratch[(size_t)TOKENS * CDIM];
// Fragment-packed tf32 weights (u64 = {b0 lo, b1 hi})
__device__ u64 g_wqkvf[2 * 12 * 36 * 32];   // K=96 (KT12), N=288 (NT36)
__device__ u64 g_w1f  [2 * 12 * 48 * 32];   // K=96,  N=384
__device__ u64 g_w2f  [2 * 48 * 12 * 32];   // K=384, N=96

#define ASMEM ((64*XW_LD + 64*QKV_LD + 3*64*S_LD + 1032) * 4)
#define MSMEM ((64*XW_LD + 64*HB_LD) * 4)

// ---- tf32 helpers ----
__device__ __forceinline__ u32 tf32bits(float x) {
    u32 r; asm("cvt.rna.tf32.f32 %0,%1;" : "=r"(r) : "f"(x)); return r;
}
__device__ __forceinline__ float tf32r(float x) {
    return __uint_as_float(tf32bits(x));
}
__device__ __forceinline__ void mma_tf32(
    float& c0, float& c1, float& c2, float& c3,
    u32 a0, u32 a1, u32 a2, u32 a3, u32 b0, u32 b1)
{
    asm("mma.sync.aligned.m16n8k8.row.col.f32.tf32.tf32.f32 "
        "{%0,%1,%2,%3},{%4,%5,%6,%7},{%8,%9},{%0,%1,%2,%3};"
        : "+f"(c0), "+f"(c1), "+f"(c2), "+f"(c3)
        : "r"(a0), "r"(a1), "r"(a2), "r"(a3), "r"(b0), "r"(b1));
}

// ---- packed fp32x2 helpers (FFMA2 path, kept for S/PV) ----
__device__ __forceinline__ u64 pk2(float x, float y) {
    u64 r; asm("mov.b64 %0,{%1,%2};" : "=l"(r) : "f"(x), "f"(y)); return r;
}
__device__ __forceinline__ void upk2(float& x, float& y, u64 v) {
    asm("mov.b64 {%0,%1},%2;" : "=f"(x), "=f"(y) : "l"(v));
}
__device__ __forceinline__ void fma2(u64& d, u64 a, u64 b) {
    asm("fma.rn.f32x2 %0,%1,%2,%0;" : "+l"(d) : "l"(a), "l"(b));
}

// ---------------------------------------------------------------------------
// Pack a row-major weight W[K][N] (per layer) into mma B-fragment order:
// dst[layer][(kt*NT+nt)*32 + lane] = { tf32(W[kt*8+tig][nt*8+gid]),
//                                      tf32(W[kt*8+tig+4][nt*8+gid]) }
// ---------------------------------------------------------------------------
__global__ void pack_kernel(const float* __restrict__ W, u64* __restrict__ dst,
                            int KT, int NT, int N, int total)
{
    int i = blockIdx.x * blockDim.x + threadIdx.x;
    if (i >= total) return;
    int per_layer = KT * NT * 32;
    int layer = i / per_layer;
    int r = i - layer * per_layer;
    int t = r >> 5, lane = r & 31;
    int kt = t / NT, nt = t - kt * NT;
    int k = kt * 8 + (lane & 3);
    int n = nt * 8 + (lane >> 2);
    const float* Wl = W + (size_t)layer * (KT * 8) * N;
    u32 lo = tf32bits(Wl[(size_t)k * N + n]);
    u32 hi = tf32bits(Wl[(size_t)(k + 4) * N + n]);
    dst[i] = ((u64)hi << 32) | lo;
}

// ---------------------------------------------------------------------------
// Attention block: LN1 -> QKV (tf32 MMA) -> S(+bias) -> softmax -> P@V -> proj
// One CTA per 4x4x4 window, 512 threads.
// ---------------------------------------------------------------------------
__global__ __launch_bounds__(512, 1) void attn_kernel(
    const float* __restrict__ x, float* __restrict__ out,
    const u64*  __restrict__ Wqkvf, const float* __restrict__ Bqkv,
    const float* __restrict__ Wp,   const float* __restrict__ Bp,
    const float* __restrict__ tb,
    const float* __restrict__ g1,   const float* __restrict__ b1,
    int shift)
{
    extern __shared__ float sm[];
    float* xw  = sm;                    // 64 x XW_LD (tf32-rounded LN out); aliased as ao
    float* qkv = xw + 64*XW_LD;         // 64 x 292
    float* S3  = qkv + 64*QKV_LD;       // 3 x 64 x 68
    float* tbl = S3 + 3*64*S_LD;        // 1029 (+3 pad)
    float* ao  = xw;                    // 64 x 96 (stride 96), reuse after QKV

    const int tid  = threadIdx.x;
    const int lane = tid & 31;
    const int warp = tid >> 5;

    const int bw   = blockIdx.x;
    const int b    = bw >> 12;
    const int widx = bw & 4095;
    const int wd   = widx >> 8;
    const int wh   = (widx >> 4) & 15;
    const int ww   = widx & 15;

    for (int i = tid; i < 1029; i += 512) tbl[i] = tb[i];

    // ---- LN1 (one warp per token), store tf32-rounded ----
    for (int t = warp; t < 64; t += 16) {
        int td = t >> 4, th = (t >> 2) & 3, tw = t & 3;
        int gd = (wd*4 + td + shift) & 63;
        int gh = (wh*4 + th + shift) & 63;
        int gw = (ww*4 + tw + shift) & 63;
        const float* src = x + (size_t)((((b*64 + gd)*64 + gh)*64 + gw)) * 96;
        float v0 = src[lane], v1 = src[lane+32], v2 = src[lane+64];
        float s  = v0 + v1 + v2;
        float sq = v0*v0 + v1*v1 + v2*v2;
        #pragma unroll
        for (int o = 16; o; o >>= 1) {
            s  += __shfl_xor_sync(0xffffffffu, s,  o);
            sq += __shfl_xor_sync(0xffffffffu, sq, o);
        }
        float mean = s * (1.0f/96.0f);
        float var  = sq * (1.0f/96.0f) - mean*mean;
        float rstd = rsqrtf(var + 1e-5f);
        xw[t*XW_LD+lane]    = tf32r((v0-mean)*rstd*g1[lane]    + b1[lane]);
        xw[t*XW_LD+lane+32] = tf32r((v1-mean)*rstd*g1[lane+32] + b1[lane+32]);
        xw[t*XW_LD+lane+64] = tf32r((v2-mean)*rstd*g1[lane+64] + b1[lane+64]);
    }
    __syncthreads();

    // ---- QKV GEMM via tf32 MMA: warp = (mt = warp&3, ng = warp>>2), 9 n-tiles ----
    {
        const int mt = warp & 3, ng = warp >> 2;
        const int gid = lane >> 2, tig = lane & 3;
        float acc[9][4];
        #pragma unroll
        for (int nt = 0; nt < 9; nt++) {
            int col0 = 72*ng + 8*nt + 2*tig;
            float2 bb = *(const float2*)&Bqkv[col0];
            acc[nt][0] = bb.x; acc[nt][1] = bb.y;
            acc[nt][2] = bb.x; acc[nt][3] = bb.y;
        }
        #pragma unroll
        for (int kt = 0; kt < 12; kt++) {
            const float* arow0 = &xw[(16*mt + gid)*XW_LD + 8*kt];
            const float* arow1 = arow0 + 8*XW_LD;
            u32 a0 = __float_as_uint(arow0[tig]);
            u32 a1 = __float_as_uint(arow1[tig]);
            u32 a2 = __float_as_uint(arow0[tig+4]);
            u32 a3 = __float_as_uint(arow1[tig+4]);
            #pragma unroll
            for (int nt = 0; nt < 9; nt++) {
                u64 w = Wqkvf[(kt*36 + ng*9 + nt)*32 + lane];
                mma_tf32(acc[nt][0], acc[nt][1], acc[nt][2], acc[nt][3],
                         a0, a1, a2, a3, (u32)w, (u32)(w >> 32));
            }
        }
        const float qs = 0.17677669529663687f;  // 32^-0.5
        #pragma unroll
        for (int nt = 0; nt < 9; nt++) {
            int col0 = 72*ng + 8*nt + 2*tig;
            float sc = (72*ng + 8*nt < 96) ? qs : 1.0f;
            *(float2*)&qkv[(16*mt + gid)*QKV_LD + col0]     = make_float2(acc[nt][0]*sc, acc[nt][1]*sc);
            *(float2*)&qkv[(16*mt + gid + 8)*QKV_LD + col0] = make_float2(acc[nt][2]*sc, acc[nt][3]*sc);
        }
    }
    __syncthreads();

    // ---- S = qK^T + bias, all heads (FFMA2 over d-pairs) ----
    #pragma unroll
    for (int h = 0; h < 3; h++) {
        u64 sacc[4][2];
        #pragma unroll
        for (int i = 0; i < 4; i++) { sacc[i][0] = 0ULL; sacc[i][1] = 0ULL; }
        const float* kp0 = &qkv[lane*QKV_LD      + 96 + h*32];
        const float* kp1 = &qkv[(lane+32)*QKV_LD + 96 + h*32];
        #pragma unroll
        for (int d4 = 0; d4 < 8; d4++) {
            ulonglong2 k0 = *(const ulonglong2*)&kp0[4*d4];
            ulonglong2 k1 = *(const ulonglong2*)&kp1[4*d4];
            #pragma unroll
            for (int i = 0; i < 4; i++) {
                ulonglong2 qv = *(const ulonglong2*)&qkv[(warp + 16*i)*QKV_LD + h*32 + 4*d4];
                fma2(sacc[i][0], qv.x, k0.x);
                fma2(sacc[i][0], qv.y, k0.y);
                fma2(sacc[i][1], qv.x, k1.x);
                fma2(sacc[i][1], qv.y, k1.y);
            }
        }
        #pragma unroll
        for (int i = 0; i < 4; i++) {
            int q = warp + 16*i;
            int qd = q >> 4, qh = (q >> 2) & 3, qw = q & 3;
            #pragma unroll
            for (int j = 0; j < 2; j++) {
                int kk = lane + 32*j;
                int kd = kk >> 4, kh = (kk >> 2) & 3, kw = kk & 3;
                int ridx = (qd-kd+3)*49 + (qh-kh+3)*7 + (qw-kw+3);
                float lo, hi; upk2(lo, hi, sacc[i][j]);
                S3[(h*64 + q)*S_LD + kk] = lo + hi + tbl[ridx*3 + h];
            }
        }
    }
    __syncthreads();

    // ---- softmax: 8 lanes per row, all heads ----
    {
        int row = tid >> 3, sub = tid & 7;
        #pragma unroll
        for (int h = 0; h < 3; h++) {
            float* Sr = &S3[(h*64 + row)*S_LD + sub*8];
            float4 v0 = *(float4*)Sr;
            float4 v1 = *(float4*)(Sr + 4);
            float vals[8] = {v0.x,v0.y,v0.z,v0.w, v1.x,v1.y,v1.z,v1.w};
            float m = vals[0];
            #pragma unroll
            for (int c = 1; c < 8; c++) m = fmaxf(m, vals[c]);
            m = fmaxf(m, __shfl_xor_sync(0xffffffffu, m, 1));
            m = fmaxf(m, __shfl_xor_sync(0xffffffffu, m, 2));
            m = fmaxf(m, __shfl_xor_sync(0xffffffffu, m, 4));
            float ssum = 0.f;
            #pragma unroll
            for (int c = 0; c < 8; c++) { vals[c] = __expf(vals[c] - m); ssum += vals[c]; }
            ssum += __shfl_xor_sync(0xffffffffu, ssum, 1);
            ssum += __shfl_xor_sync(0xffffffffu, ssum, 2);
            ssum += __shfl_xor_sync(0xffffffffu, ssum, 4);
            float inv = 1.0f / ssum;
            *(float4*)Sr       = make_float4(vals[0]*inv, vals[1]*inv, vals[2]*inv, vals[3]*inv);
            *(float4*)(Sr + 4) = make_float4(vals[4]*inv, vals[5]*inv, vals[6]*inv, vals[7]*inv);
        }
    }
    __syncthreads();

    // ---- P@V, all heads (FFMA2 over k-pairs) ----
    {
        u64 oacc[4][3];
        #pragma unroll
        for (int i = 0; i < 4; i++)
            #pragma unroll
            for (int h = 0; h < 3; h++) oacc[i][h] = 0ULL;
        for (int k4 = 0; k4 < 16; k4++) {
            #pragma unroll
            for (int h = 0; h < 3; h++) {
                float v0 = qkv[(4*k4+0)*QKV_LD + 192 + h*32 + lane];
                float v1 = qkv[(4*k4+1)*QKV_LD + 192 + h*32 + lane];
                float v2 = qkv[(4*k4+2)*QKV_LD + 192 + h*32 + lane];
                float v3 = qkv[(4*k4+3)*QKV_LD + 192 + h*32 + lane];
                u64 vp0 = pk2(v0, v1), vp1 = pk2(v2, v3);
                #pragma unroll
                for (int i = 0; i < 4; i++) {
                    ulonglong2 s = *(const ulonglong2*)&S3[(h*64 + warp + 16*i)*S_LD + 4*k4];
                    fma2(oacc[i][h], s.x, vp0);
                    fma2(oacc[i][h], s.y, vp1);
                }
            }
        }
        __syncthreads();   // xw buffer about to be overwritten as ao
        #pragma unroll
        for (int i = 0; i < 4; i++)
            #pragma unroll
            for (int h = 0; h < 3; h++) {
                float lo, hi; upk2(lo, hi, oacc[i][h]);
                ao[(warp + 16*i)*96 + h*32 + lane] = lo + hi;
            }
    }
    __syncthreads();

    // ---- proj + residual (FFMA path, residual re-read from x) ----
    {
        float pacc[4][3];
        float2 bb = *(const float2*)&Bp[2*lane];
        float  b3 = Bp[64 + lane];
        #pragma unroll
        for (int i = 0; i < 4; i++) { pacc[i][0] = bb.x; pacc[i][1] = bb.y; pacc[i][2] = b3; }
        for (int k4 = 0; k4 < 24; k4++) {
            float a[4][4];
            #pragma unroll
            for (int i = 0; i < 4; i++) {
                float4 v = *(const float4*)&ao[(warp + 16*i)*96 + 4*k4];
                a[i][0]=v.x; a[i][1]=v.y; a[i][2]=v.z; a[i][3]=v.w;
            }
            #pragma unroll
            for (int kk = 0; kk < 4; kk++) {
                int k = 4*k4 + kk;
                float2 w  = *(const float2*)&Wp[k*96 + 2*lane];
                float  w3 = Wp[k*96 + 64 + lane];
                #pragma unroll
                for (int i = 0; i < 4; i++) {
                    pacc[i][0] += a[i][kk]*w.x;
                    pacc[i][1] += a[i][kk]*w.y;
                    pacc[i][2] += a[i][kk]*w3;
                }
            }
        }
        #pragma unroll
        for (int i = 0; i < 4; i++) {
            int t = warp + 16*i;
            int td = t >> 4, th = (t >> 2) & 3, tw = t & 3;
            int gd = (wd*4 + td + shift) & 63;
            int gh = (wh*4 + th + shift) & 63;
            int gw = (ww*4 + tw + shift) & 63;
            size_t idx = (size_t)((((b*64 + gd)*64 + gh)*64 + gw)) * 96;
            const float* rx = x + idx;
            float* dst = out + idx;
            dst[2*lane]   = pacc[i][0] + rx[2*lane];
            dst[2*lane+1] = pacc[i][1] + rx[2*lane+1];
            dst[64+lane]  = pacc[i][2] + rx[64+lane];
        }
    }
}

// ---------------------------------------------------------------------------
// MLP block: LN2 -> GEMM1 (tf32 MMA) -> exact GELU -> GEMM2 (tf32 MMA)
// -> +residual, in-place. One CTA per 64 tokens, 512 threads.
// ---------------------------------------------------------------------------
__global__ __launch_bounds__(512, 1) void mlp_kernel(
    float* __restrict__ xa,
    const float* __restrict__ g2, const float* __restrict__ b2ln,
    const u64*  __restrict__ W1f, const float* __restrict__ B1,
    const u64*  __restrict__ W2f, const float* __restrict__ B2)
{
    extern __shared__ float sm[];
    float* y  = sm;             // 64 x XW_LD (tf32-rounded LN out)
    float* hb = y + 64*XW_LD;   // 64 x HB_LD (tf32-rounded GELU out)

    const int tid  = threadIdx.x;
    const int lane = tid & 31;
    const int warp = tid >> 5;
    const size_t base = (size_t)blockIdx.x * 64;

    const int mt = warp & 3, ng = warp >> 2;
    const int gid = lane >> 2, tig = lane & 3;

    // ---- LN2 ----
    for (int t = warp; t < 64; t += 16) {
        const float* src = xa + (base + t) * 96;
        float v0 = src[lane], v1 = src[lane+32], v2 = src[lane+64];
        float s  = v0 + v1 + v2;
        float sq = v0*v0 + v1*v1 + v2*v2;
        #pragma unroll
        for (int o = 16; o; o >>= 1) {
            s  += __shfl_xor_sync(0xffffffffu, s,  o);
            sq += __shfl_xor_sync(0xffffffffu, sq, o);
        }
        float mean = s * (1.0f/96.0f);
        float var  = sq * (1.0f/96.0f) - mean*mean;
        float rstd = rsqrtf(var + 1e-5f);
        y[t*XW_LD+lane]    = tf32r((v0-mean)*rstd*g2[lane]    + b2ln[lane]);
        y[t*XW_LD+lane+32] = tf32r((v1-mean)*rstd*g2[lane+32] + b2ln[lane+32]);
        y[t*XW_LD+lane+64] = tf32r((v2-mean)*rstd*g2[lane+64] + b2ln[lane+64]);
    }
    __syncthreads();

    // ---- GEMM1: (64x96)@(96x384) via MMA; warp: mt rows16, ng -> 12 n-tiles ----
    {
        float acc[12][4];
        #pragma unroll
        for (int nt = 0; nt < 12; nt++)
            acc[nt][0] = acc[nt][1] = acc[nt][2] = acc[nt][3] = 0.f;
        #pragma unroll
        for (int kt = 0; kt < 12; kt++) {
            const float* arow0 = &y[(16*mt + gid)*XW_LD + 8*kt];
            const float* arow1 = arow0 + 8*XW_LD;
            u32 a0 = __float_as_uint(arow0[tig]);
            u32 a1 = __float_as_uint(arow1[tig]);
            u32 a2 = __float_as_uint(arow0[tig+4]);
            u32 a3 = __float_as_uint(arow1[tig+4]);
            #pragma unroll
            for (int nt = 0; nt < 12; nt++) {
                u64 w = W1f[(kt*48 + ng*12 + nt)*32 + lane];
                mma_tf32(acc[nt][0], acc[nt][1], acc[nt][2], acc[nt][3],
                         a0, a1, a2, a3, (u32)w, (u32)(w >> 32));
            }
        }
        // bias + exact GELU + store (tf32-rounded)
        #pragma unroll
        for (int nt = 0; nt < 12; nt++) {
            int col0 = 96*ng + 8*nt + 2*tig;
            float2 bb = *(const float2*)&B1[col0];
            float u0 = acc[nt][0] + bb.x, u1 = acc[nt][1] + bb.y;
            float u2 = acc[nt][2] + bb.x, u3 = acc[nt][3] + bb.y;
            float g0 = 0.5f*u0*(1.0f + erff(u0*0.70710678118654752f));
            float g1v= 0.5f*u1*(1.0f + erff(u1*0.70710678118654752f));
            float g2v= 0.5f*u2*(1.0f + erff(u2*0.70710678118654752f));
            float g3 = 0.5f*u3*(1.0f + erff(u3*0.70710678118654752f));
            *(float2*)&hb[(16*mt + gid)*HB_LD + col0]     = make_float2(tf32r(g0), tf32r(g1v));
            *(float2*)&hb[(16*mt + gid + 8)*HB_LD + col0] = make_float2(tf32r(g2v), tf32r(g3));
        }
    }
    __syncthreads();

    // ---- GEMM2: (64x384)@(384x96) via MMA; warp: mt rows16, ng -> 3 n-tiles ----
    {
        float acc[3][4];
        #pragma unroll
        for (int nt = 0; nt < 3; nt++)
            acc[nt][0] = acc[nt][1] = acc[nt][2] = acc[nt][3] = 0.f;
        #pragma unroll
        for (int kt = 0; kt < 48; kt++) {
            const float* arow0 = &hb[(16*mt + gid)*HB_LD + 8*kt];
            const float* arow1 = arow0 + 8*HB_LD;
            u32 a0 = __float_as_uint(arow0[tig]);
            u32 a1 = __float_as_uint(arow1[tig]);
            u32 a2 = __float_as_uint(arow0[tig+4]);
            u32 a3 = __float_as_uint(arow1[tig+4]);
            #pragma unroll
            for (int nt = 0; nt < 3; nt++) {
                u64 w = W2f[(kt*12 + ng*3 + nt)*32 + lane];
                mma_tf32(acc[nt][0], acc[nt][1], acc[nt][2], acc[nt][3],
                         a0, a1, a2, a3, (u32)w, (u32)(w >> 32));
            }
        }
        // bias + residual, write back in place
        #pragma unroll
        for (int nt = 0; nt < 3; nt++) {
            int col0 = 24*ng + 8*nt + 2*tig;
            float2 bb = *(const float2*)&B2[col0];
            float* p0 = xa + (base + 16*mt + gid) * 96 + col0;
            float* p1 = xa + (base + 16*mt + gid + 8) * 96 + col0;
            float2 r0 = *(float2*)p0;
            float2 r1 = *(float2*)p1;
            *(float2*)p0 = make_float2(acc[nt][0] + bb.x + r0.x, acc[nt][1] + bb.y + r0.y);
            *(float2*)p1 = make_float2(acc[nt][2] + bb.x + r1.x, acc[nt][3] + bb.y + r1.y);
        }
    }
}

// ---------------------------------------------------------------------------
extern "C" void kernel_launch(void* const* d_in, const int* in_sizes, int n_in,
                              void* d_out, int out_size)
{
    const float* x      = (const float*)d_in[0];
    const float* qkv_w  = (const float*)d_in[1];
    const float* qkv_b  = (const float*)d_in[2];
    const float* proj_w = (const float*)d_in[3];
    const float* proj_b = (const float*)d_in[4];
    const float* btab   = (const float*)d_in[5];
    const float* ln1g   = (const float*)d_in[6];
    const float* ln1b   = (const float*)d_in[7];
    const float* ln2g   = (const float*)d_in[8];
    const float* ln2b   = (const float*)d_in[9];
    const float* w1     = (const float*)d_in[10];
    const float* b1     = (const float*)d_in[11];
    const float* w2     = (const float*)d_in[12];
    const float* b2     = (const float*)d_in[13];
    float* out = (float*)d_out;

    float* scratch = nullptr;
    u64 *wqkvf = nullptr, *w1f = nullptr, *w2f = nullptr;
    cudaGetSymbolAddress((void**)&scratch, g_scratch);
    cudaGetSymbolAddress((void**)&wqkvf,   g_wqkvf);
    cudaGetSymbolAddress((void**)&w1f,     g_w1f);
    cudaGetSymbolAddress((void**)&w2f,     g_w2f);

    cudaFuncSetAttribute(attn_kernel, cudaFuncAttributeMaxDynamicSharedMemorySize, ASMEM);
    cudaFuncSetAttribute(mlp_kernel,  cudaFuncAttributeMaxDynamicSharedMemorySize, MSMEM);

    // Fragment-pack weights (both layers each)
    {
        int tq = 2*12*36*32, t1 = 2*12*48*32, t2 = 2*48*12*32;
        pack_kernel<<<(tq+255)/256, 256>>>(qkv_w, wqkvf, 12, 36, 288, tq);
        pack_kernel<<<(t1+255)/256, 256>>>(w1,    w1f,   12, 48, 384, t1);
        pack_kernel<<<(t2+255)/256, 256>>>(w2,    w2f,   48, 12,  96, t2);
    }

    // ---- block 0 (shift 0) ----
    attn_kernel<<<NWIN, 512, ASMEM>>>(x, scratch,
        wqkvf, qkv_b, proj_w, proj_b, btab, ln1g, ln1b, 0);
    mlp_kernel<<<TOKENS/64, 512, MSMEM>>>(scratch,
        ln2g, ln2b, w1f, b1, w2f, b2);

    // ---- block 1 (shift 2) ----
    attn_kernel<<<NWIN, 512, ASMEM>>>(scratch, out,
        wqkvf + 12*36*32, qkv_b + 288, proj_w + 96*96, proj_b + 96,
        btab + 343*3, ln1g + 96, ln1b + 96, 2);
    mlp_kernel<<<TOKENS/64, 512, MSMEM>>>(out,
        ln2g + 96, ln2b + 96, w1f + 12*48*32, b1 + 384, w2f + 48*12*32, b2 + 96);
}

// round 8
// speedup vs baseline: 3.7067x; 1.3135x over previous
#include <cuda_runtime.h>
#include <math.h>

typedef unsigned long long u64;
typedef unsigned int u32;

#define CDIM   96
#define NWIN   8192
#define TOKENS (2*64*64*64)
#define QKV_LD 292          // %32==4, 16B-aligned rows
#define S_LD   68
#define XW_LD  100          // %32==4 -> conflict-free mma A-fragment LDS
#define HB_LD  388          // %32==4

// Static device scratch (no allocs allowed)
__device__ float g_scratch[(size_t)TOKENS * CDIM];
// Fragment-packed tf32 weights (u64 = {b0 lo, b1 hi})
__device__ u64 g_wqkvf[2 * 12 * 36 * 32];   // K=96 (KT12), N=288 (NT36)
__device__ u64 g_w1f  [2 * 12 * 48 * 32];   // K=96,  N=384
__device__ u64 g_w2f  [2 * 48 * 12 * 32];   // K=384, N=96
__device__ u64 g_wpf  [2 * 12 * 12 * 32];   // K=96,  N=96 (proj)
// Dense rel-pos bias: [layer][head][q=64][k=64]
__device__ float g_bias[2 * 3 * 64 * 64];

#define ASMEM ((64*XW_LD + 64*QKV_LD + 3*64*S_LD) * 4)
#define MSMEM ((64*XW_LD + 64*HB_LD) * 4)

// ---- tf32 helpers ----
__device__ __forceinline__ u32 tf32bits(float x) {
    u32 r; asm("cvt.rna.tf32.f32 %0,%1;" : "=r"(r) : "f"(x)); return r;
}
__device__ __forceinline__ float tf32r(float x) {
    return __uint_as_float(tf32bits(x));
}
__device__ __forceinline__ void mma_tf32(
    float& c0, float& c1, float& c2, float& c3,
    u32 a0, u32 a1, u32 a2, u32 a3, u32 b0, u32 b1)
{
    asm("mma.sync.aligned.m16n8k8.row.col.f32.tf32.tf32.f32 "
        "{%0,%1,%2,%3},{%4,%5,%6,%7},{%8,%9},{%0,%1,%2,%3};"
        : "+f"(c0), "+f"(c1), "+f"(c2), "+f"(c3)
        : "r"(a0), "r"(a1), "r"(a2), "r"(a3), "r"(b0), "r"(b1));
}

// ---------------------------------------------------------------------------
// Pack row-major W[K][N] (per layer) into mma B-fragment order.
// ---------------------------------------------------------------------------
__global__ void pack_kernel(const float* __restrict__ W, u64* __restrict__ dst,
                            int KT, int NT, int N, int total)
{
    int i = blockIdx.x * blockDim.x + threadIdx.x;
    if (i >= total) return;
    int per_layer = KT * NT * 32;
    int layer = i / per_layer;
    int r = i - layer * per_layer;
    int t = r >> 5, lane = r & 31;
    int kt = t / NT, nt = t - kt * NT;
    int k = kt * 8 + (lane & 3);
    int n = nt * 8 + (lane >> 2);
    const float* Wl = W + (size_t)layer * (KT * 8) * N;
    u32 lo = tf32bits(Wl[(size_t)k * N + n]);
    u32 hi = tf32bits(Wl[(size_t)(k + 4) * N + n]);
    dst[i] = ((u64)hi << 32) | lo;
}

// ---------------------------------------------------------------------------
// Precompute dense rel-pos bias matrices (window-invariant).
// ---------------------------------------------------------------------------
__global__ void bias_kernel(const float* __restrict__ tb) {
    int i = blockIdx.x * blockDim.x + threadIdx.x;
    if (i >= 2*3*64*64) return;
    int layer = i / (3*4096);
    int r = i % (3*4096);
    int h = r / 4096;
    int qk = r & 4095;
    int q = qk >> 6, k = qk & 63;
    int qd = q >> 4, qh = (q >> 2) & 3, qw = q & 3;
    int kd = k >> 4, kh = (k >> 2) & 3, kw = k & 3;
    int ridx = (qd-kd+3)*49 + (qh-kh+3)*7 + (qw-kw+3);
    g_bias[i] = tb[layer*1029 + ridx*3 + h];
}

// ---------------------------------------------------------------------------
// Attention block, all GEMMs on tensor cores.
// One CTA per 4x4x4 window, 512 threads (16 warps: mt=warp&3, ng=warp>>2).
// ---------------------------------------------------------------------------
__global__ __launch_bounds__(512, 1) void attn_kernel(
    const float* __restrict__ x, float* __restrict__ out,
    const u64*  __restrict__ Wqkvf, const float* __restrict__ Bqkv,
    const u64*  __restrict__ Wpf,   const float* __restrict__ Bp,
    const float* __restrict__ biasM,
    const float* __restrict__ g1,   const float* __restrict__ b1,
    int shift)
{
    extern __shared__ float sm[];
    float* xw  = sm;                    // 64 x XW_LD; later aliased as ao
    float* qkv = xw + 64*XW_LD;         // 64 x 292 (tf32-rounded)
    float* S3  = qkv + 64*QKV_LD;       // 3 x 64 x 68
    float* ao  = xw;

    const int tid  = threadIdx.x;
    const int lane = tid & 31;
    const int warp = tid >> 5;
    const int mt   = warp & 3;
    const int ng   = warp >> 2;
    const int gid  = lane >> 2;
    const int tig  = lane & 3;

    const int bw   = blockIdx.x;
    const int b    = bw >> 12;
    const int widx = bw & 4095;
    const int wd   = widx >> 8;
    const int wh   = (widx >> 4) & 15;
    const int ww   = widx & 15;

    // ---- LN1 (one warp per token), store tf32-rounded ----
    for (int t = warp; t < 64; t += 16) {
        int td = t >> 4, th = (t >> 2) & 3, tw = t & 3;
        int gd = (wd*4 + td + shift) & 63;
        int gh = (wh*4 + th + shift) & 63;
        int gw = (ww*4 + tw + shift) & 63;
        const float* src = x + (size_t)((((b*64 + gd)*64 + gh)*64 + gw)) * 96;
        float v0 = src[lane], v1 = src[lane+32], v2 = src[lane+64];
        float s  = v0 + v1 + v2;
        float sq = v0*v0 + v1*v1 + v2*v2;
        #pragma unroll
        for (int o = 16; o; o >>= 1) {
            s  += __shfl_xor_sync(0xffffffffu, s,  o);
            sq += __shfl_xor_sync(0xffffffffu, sq, o);
        }
        float mean = s * (1.0f/96.0f);
        float var  = sq * (1.0f/96.0f) - mean*mean;
        float rstd = rsqrtf(var + 1e-5f);
        xw[t*XW_LD+lane]    = tf32r((v0-mean)*rstd*g1[lane]    + b1[lane]);
        xw[t*XW_LD+lane+32] = tf32r((v1-mean)*rstd*g1[lane+32] + b1[lane+32]);
        xw[t*XW_LD+lane+64] = tf32r((v2-mean)*rstd*g1[lane+64] + b1[lane+64]);
    }
    __syncthreads();

    // ---- QKV GEMM (MMA): 9 n-tiles per warp; outputs tf32-rounded, q scaled ----
    {
        float acc[9][4];
        #pragma unroll
        for (int nt = 0; nt < 9; nt++) {
            int col0 = 72*ng + 8*nt + 2*tig;
            float2 bb = *(const float2*)&Bqkv[col0];
            acc[nt][0] = bb.x; acc[nt][1] = bb.y;
            acc[nt][2] = bb.x; acc[nt][3] = bb.y;
        }
        #pragma unroll
        for (int kt = 0; kt < 12; kt++) {
            const float* arow0 = &xw[(16*mt + gid)*XW_LD + 8*kt];
            const float* arow1 = arow0 + 8*XW_LD;
            u32 a0 = __float_as_uint(arow0[tig]);
            u32 a1 = __float_as_uint(arow1[tig]);
            u32 a2 = __float_as_uint(arow0[tig+4]);
            u32 a3 = __float_as_uint(arow1[tig+4]);
            #pragma unroll
            for (int nt = 0; nt < 9; nt++) {
                u64 w = Wqkvf[(kt*36 + ng*9 + nt)*32 + lane];
                mma_tf32(acc[nt][0], acc[nt][1], acc[nt][2], acc[nt][3],
                         a0, a1, a2, a3, (u32)w, (u32)(w >> 32));
            }
        }
        const float qs = 0.17677669529663687f;  // 32^-0.5
        #pragma unroll
        for (int nt = 0; nt < 9; nt++) {
            int col0 = 72*ng + 8*nt + 2*tig;
            float sc = (72*ng + 8*nt < 96) ? qs : 1.0f;
            *(float2*)&qkv[(16*mt + gid)*QKV_LD + col0] =
                make_float2(tf32r(acc[nt][0]*sc), tf32r(acc[nt][1]*sc));
            *(float2*)&qkv[(16*mt + gid + 8)*QKV_LD + col0] =
                make_float2(tf32r(acc[nt][2]*sc), tf32r(acc[nt][3]*sc));
        }
    }
    __syncthreads();

    // ---- S = qK^T + bias (MMA): per head, ng covers 16 cols (2 n-tiles) ----
    #pragma unroll
    for (int h = 0; h < 3; h++) {
        float acc[2][4];
        #pragma unroll
        for (int j = 0; j < 2; j++)
            acc[j][0] = acc[j][1] = acc[j][2] = acc[j][3] = 0.f;
        #pragma unroll
        for (int ks = 0; ks < 4; ks++) {
            const float* ap = &qkv[(16*mt + gid)*QKV_LD + h*32 + 8*ks];
            u32 a0 = __float_as_uint(ap[tig]);
            u32 a1 = __float_as_uint(ap[8*QKV_LD + tig]);
            u32 a2 = __float_as_uint(ap[tig+4]);
            u32 a3 = __float_as_uint(ap[8*QKV_LD + tig+4]);
            #pragma unroll
            for (int j = 0; j < 2; j++) {
                const float* bp = &qkv[(ng*16 + j*8 + gid)*QKV_LD + 96 + h*32 + 8*ks];
                u32 b0 = __float_as_uint(bp[tig]);
                u32 b1 = __float_as_uint(bp[tig+4]);
                mma_tf32(acc[j][0], acc[j][1], acc[j][2], acc[j][3],
                         a0, a1, a2, a3, b0, b1);
            }
        }
        const float* bh = biasM + h*4096;
        #pragma unroll
        for (int j = 0; j < 2; j++) {
            int col = ng*16 + j*8 + 2*tig;
            int q0  = 16*mt + gid;
            float2 bb0 = *(const float2*)&bh[q0*64 + col];
            float2 bb1 = *(const float2*)&bh[(q0+8)*64 + col];
            *(float2*)&S3[(h*64 + q0)*S_LD + col] =
                make_float2(acc[j][0] + bb0.x, acc[j][1] + bb0.y);
            *(float2*)&S3[(h*64 + q0 + 8)*S_LD + col] =
                make_float2(acc[j][2] + bb1.x, acc[j][3] + bb1.y);
        }
    }
    __syncthreads();

    // ---- softmax: 8 lanes per row, all heads; probs tf32-rounded ----
    {
        int row = tid >> 3, sub = tid & 7;
        #pragma unroll
        for (int h = 0; h < 3; h++) {
            float* Sr = &S3[(h*64 + row)*S_LD + sub*8];
            float4 v0 = *(float4*)Sr;
            float4 v1 = *(float4*)(Sr + 4);
            float vals[8] = {v0.x,v0.y,v0.z,v0.w, v1.x,v1.y,v1.z,v1.w};
            float m = vals[0];
            #pragma unroll
            for (int c = 1; c < 8; c++) m = fmaxf(m, vals[c]);
            m = fmaxf(m, __shfl_xor_sync(0xffffffffu, m, 1));
            m = fmaxf(m, __shfl_xor_sync(0xffffffffu, m, 2));
            m = fmaxf(m, __shfl_xor_sync(0xffffffffu, m, 4));
            float ssum = 0.f;
            #pragma unroll
            for (int c = 0; c < 8; c++) { vals[c] = __expf(vals[c] - m); ssum += vals[c]; }
            ssum += __shfl_xor_sync(0xffffffffu, ssum, 1);
            ssum += __shfl_xor_sync(0xffffffffu, ssum, 2);
            ssum += __shfl_xor_sync(0xffffffffu, ssum, 4);
            float inv = 1.0f / ssum;
            *(float4*)Sr = make_float4(tf32r(vals[0]*inv), tf32r(vals[1]*inv),
                                       tf32r(vals[2]*inv), tf32r(vals[3]*inv));
            *(float4*)(Sr+4) = make_float4(tf32r(vals[4]*inv), tf32r(vals[5]*inv),
                                           tf32r(vals[6]*inv), tf32r(vals[7]*inv));
        }
    }
    __syncthreads();

    // ---- P@V (MMA): output 64x96, ng covers 24 cols (3 n-tiles) ----
    {
        float acc[3][4];
        #pragma unroll
        for (int j = 0; j < 3; j++)
            acc[j][0] = acc[j][1] = acc[j][2] = acc[j][3] = 0.f;
        #pragma unroll
        for (int j = 0; j < 3; j++) {
            int ct = ng*24 + j*8;
            int h  = ct >> 5;
            int dc = ct & 31;
            #pragma unroll
            for (int ks = 0; ks < 8; ks++) {
                const float* ap = &S3[(h*64 + 16*mt + gid)*S_LD + 8*ks];
                u32 a0 = __float_as_uint(ap[tig]);
                u32 a1 = __float_as_uint(ap[8*S_LD + tig]);
                u32 a2 = __float_as_uint(ap[tig+4]);
                u32 a3 = __float_as_uint(ap[8*S_LD + tig+4]);
                const float* bp = &qkv[(8*ks + tig)*QKV_LD + 192 + h*32 + dc + gid];
                u32 b0 = __float_as_uint(bp[0]);
                u32 b1 = __float_as_uint(bp[4*QKV_LD]);
                mma_tf32(acc[j][0], acc[j][1], acc[j][2], acc[j][3],
                         a0, a1, a2, a3, b0, b1);
            }
        }
        __syncthreads();   // xw/ao alias: ensure no one still needs xw (dead) / ordering
        #pragma unroll
        for (int j = 0; j < 3; j++) {
            int ct = ng*24 + j*8 + 2*tig;
            *(float2*)&ao[(16*mt + gid)*XW_LD + ct] =
                make_float2(tf32r(acc[j][0]), tf32r(acc[j][1]));
            *(float2*)&ao[(16*mt + gid + 8)*XW_LD + ct] =
                make_float2(tf32r(acc[j][2]), tf32r(acc[j][3]));
        }
    }
    __syncthreads();

    // ---- proj (MMA) + bias + residual -> global (shifted) ----
    {
        float acc[3][4];
        #pragma unroll
        for (int j = 0; j < 3; j++)
            acc[j][0] = acc[j][1] = acc[j][2] = acc[j][3] = 0.f;
        #pragma unroll
        for (int kt = 0; kt < 12; kt++) {
            const float* ap = &ao[(16*mt + gid)*XW_LD + 8*kt];
            u32 a0 = __float_as_uint(ap[tig]);
            u32 a1 = __float_as_uint(ap[8*XW_LD + tig]);
            u32 a2 = __float_as_uint(ap[tig+4]);
            u32 a3 = __float_as_uint(ap[8*XW_LD + tig+4]);
            #pragma unroll
            for (int j = 0; j < 3; j++) {
                u64 w = Wpf[(kt*12 + ng*3 + j)*32 + lane];
                mma_tf32(acc[j][0], acc[j][1], acc[j][2], acc[j][3],
                         a0, a1, a2, a3, (u32)w, (u32)(w >> 32));
            }
        }
        // epilogue: two rows per fragment
        int q0 = 16*mt + gid;
        #pragma unroll
        for (int rr = 0; rr < 2; rr++) {
            int t = q0 + 8*rr;
            int td = t >> 4, th = (t >> 2) & 3, tw = t & 3;
            int gd = (wd*4 + td + shift) & 63;
            int gh = (wh*4 + th + shift) & 63;
            int gw = (ww*4 + tw + shift) & 63;
            size_t idx = (size_t)((((b*64 + gd)*64 + gh)*64 + gw)) * 96;
            const float* rx = x + idx;
            float* dst = out + idx;
            #pragma unroll
            for (int j = 0; j < 3; j++) {
                int ct = ng*24 + j*8 + 2*tig;
                float2 bb = *(const float2*)&Bp[ct];
                float2 rv = *(const float2*)&rx[ct];
                *(float2*)&dst[ct] = make_float2(
                    acc[j][2*rr]   + bb.x + rv.x,
                    acc[j][2*rr+1] + bb.y + rv.y);
            }
        }
    }
}

// ---------------------------------------------------------------------------
// MLP block (unchanged from R7): LN2 -> GEMM1(MMA) -> GELU -> GEMM2(MMA)
// ---------------------------------------------------------------------------
__global__ __launch_bounds__(512, 1) void mlp_kernel(
    float* __restrict__ xa,
    const float* __restrict__ g2, const float* __restrict__ b2ln,
    const u64*  __restrict__ W1f, const float* __restrict__ B1,
    const u64*  __restrict__ W2f, const float* __restrict__ B2)
{
    extern __shared__ float sm[];
    float* y  = sm;             // 64 x XW_LD
    float* hb = y + 64*XW_LD;   // 64 x HB_LD

    const int tid  = threadIdx.x;
    const int lane = tid & 31;
    const int warp = tid >> 5;
    const size_t base = (size_t)blockIdx.x * 64;

    const int mt = warp & 3, ng = warp >> 2;
    const int gid = lane >> 2, tig = lane & 3;

    for (int t = warp; t < 64; t += 16) {
        const float* src = xa + (base + t) * 96;
        float v0 = src[lane], v1 = src[lane+32], v2 = src[lane+64];
        float s  = v0 + v1 + v2;
        float sq = v0*v0 + v1*v1 + v2*v2;
        #pragma unroll
        for (int o = 16; o; o >>= 1) {
            s  += __shfl_xor_sync(0xffffffffu, s,  o);
            sq += __shfl_xor_sync(0xffffffffu, sq, o);
        }
        float mean = s * (1.0f/96.0f);
        float var  = sq * (1.0f/96.0f) - mean*mean;
        float rstd = rsqrtf(var + 1e-5f);
        y[t*XW_LD+lane]    = tf32r((v0-mean)*rstd*g2[lane]    + b2ln[lane]);
        y[t*XW_LD+lane+32] = tf32r((v1-mean)*rstd*g2[lane+32] + b2ln[lane+32]);
        y[t*XW_LD+lane+64] = tf32r((v2-mean)*rstd*g2[lane+64] + b2ln[lane+64]);
    }
    __syncthreads();

    {
        float acc[12][4];
        #pragma unroll
        for (int nt = 0; nt < 12; nt++)
            acc[nt][0] = acc[nt][1] = acc[nt][2] = acc[nt][3] = 0.f;
        #pragma unroll
        for (int kt = 0; kt < 12; kt++) {
            const float* arow0 = &y[(16*mt + gid)*XW_LD + 8*kt];
            const float* arow1 = arow0 + 8*XW_LD;
            u32 a0 = __float_as_uint(arow0[tig]);
            u32 a1 = __float_as_uint(arow1[tig]);
            u32 a2 = __float_as_uint(arow0[tig+4]);
            u32 a3 = __float_as_uint(arow1[tig+4]);
            #pragma unroll
            for (int nt = 0; nt < 12; nt++) {
                u64 w = W1f[(kt*48 + ng*12 + nt)*32 + lane];
                mma_tf32(acc[nt][0], acc[nt][1], acc[nt][2], acc[nt][3],
                         a0, a1, a2, a3, (u32)w, (u32)(w >> 32));
            }
        }
        #pragma unroll
        for (int nt = 0; nt < 12; nt++) {
            int col0 = 96*ng + 8*nt + 2*tig;
            float2 bb = *(const float2*)&B1[col0];
            float u0 = acc[nt][0] + bb.x, u1 = acc[nt][1] + bb.y;
            float u2 = acc[nt][2] + bb.x, u3 = acc[nt][3] + bb.y;
            float g0 = 0.5f*u0*(1.0f + erff(u0*0.70710678118654752f));
            float g1v= 0.5f*u1*(1.0f + erff(u1*0.70710678118654752f));
            float g2v= 0.5f*u2*(1.0f + erff(u2*0.70710678118654752f));
            float g3 = 0.5f*u3*(1.0f + erff(u3*0.70710678118654752f));
            *(float2*)&hb[(16*mt + gid)*HB_LD + col0]     = make_float2(tf32r(g0), tf32r(g1v));
            *(float2*)&hb[(16*mt + gid + 8)*HB_LD + col0] = make_float2(tf32r(g2v), tf32r(g3));
        }
    }
    __syncthreads();

    {
        float acc[3][4];
        #pragma unroll
        for (int nt = 0; nt < 3; nt++)
            acc[nt][0] = acc[nt][1] = acc[nt][2] = acc[nt][3] = 0.f;
        #pragma unroll
        for (int kt = 0; kt < 48; kt++) {
            const float* arow0 = &hb[(16*mt + gid)*HB_LD + 8*kt];
            const float* arow1 = arow0 + 8*HB_LD;
            u32 a0 = __float_as_uint(arow0[tig]);
            u32 a1 = __float_as_uint(arow1[tig]);
            u32 a2 = __float_as_uint(arow0[tig+4]);
            u32 a3 = __float_as_uint(arow1[tig+4]);
            #pragma unroll
            for (int nt = 0; nt < 3; nt++) {
                u64 w = W2f[(kt*12 + ng*3 + nt)*32 + lane];
                mma_tf32(acc[nt][0], acc[nt][1], acc[nt][2], acc[nt][3],
                         a0, a1, a2, a3, (u32)w, (u32)(w >> 32));
            }
        }
        #pragma unroll
        for (int nt = 0; nt < 3; nt++) {
            int col0 = 24*ng + 8*nt + 2*tig;
            float2 bb = *(const float2*)&B2[col0];
            float* p0 = xa + (base + 16*mt + gid) * 96 + col0;
            float* p1 = xa + (base + 16*mt + gid + 8) * 96 + col0;
            float2 r0 = *(float2*)p0;
            float2 r1 = *(float2*)p1;
            *(float2*)p0 = make_float2(acc[nt][0] + bb.x + r0.x, acc[nt][1] + bb.y + r0.y);
            *(float2*)p1 = make_float2(acc[nt][2] + bb.x + r1.x, acc[nt][3] + bb.y + r1.y);
        }
    }
}

// ---------------------------------------------------------------------------
extern "C" void kernel_launch(void* const* d_in, const int* in_sizes, int n_in,
                              void* d_out, int out_size)
{
    const float* x      = (const float*)d_in[0];
    const float* qkv_w  = (const float*)d_in[1];
    const float* qkv_b  = (const float*)d_in[2];
    const float* proj_w = (const float*)d_in[3];
    const float* proj_b = (const float*)d_in[4];
    const float* btab   = (const float*)d_in[5];
    const float* ln1g   = (const float*)d_in[6];
    const float* ln1b   = (const float*)d_in[7];
    const float* ln2g   = (const float*)d_in[8];
    const float* ln2b   = (const float*)d_in[9];
    const float* w1     = (const float*)d_in[10];
    const float* b1     = (const float*)d_in[11];
    const float* w2     = (const float*)d_in[12];
    const float* b2     = (const float*)d_in[13];
    float* out = (float*)d_out;

    float* scratch = nullptr;
    u64 *wqkvf = nullptr, *w1f = nullptr, *w2f = nullptr, *wpf = nullptr;
    float* biasm = nullptr;
    cudaGetSymbolAddress((void**)&scratch, g_scratch);
    cudaGetSymbolAddress((void**)&wqkvf,   g_wqkvf);
    cudaGetSymbolAddress((void**)&w1f,     g_w1f);
    cudaGetSymbolAddress((void**)&w2f,     g_w2f);
    cudaGetSymbolAddress((void**)&wpf,     g_wpf);
    cudaGetSymbolAddress((void**)&biasm,   g_bias);

    cudaFuncSetAttribute(attn_kernel, cudaFuncAttributeMaxDynamicSharedMemorySize, ASMEM);
    cudaFuncSetAttribute(mlp_kernel,  cudaFuncAttributeMaxDynamicSharedMemorySize, MSMEM);

    // Prep: fragment-pack weights + dense bias matrices
    {
        int tq = 2*12*36*32, t1 = 2*12*48*32, t2 = 2*48*12*32, tp = 2*12*12*32;
        pack_kernel<<<(tq+255)/256, 256>>>(qkv_w, wqkvf, 12, 36, 288, tq);
        pack_kernel<<<(t1+255)/256, 256>>>(w1,    w1f,   12, 48, 384, t1);
        pack_kernel<<<(t2+255)/256, 256>>>(w2,    w2f,   48, 12,  96, t2);
        pack_kernel<<<(tp+255)/256, 256>>>(proj_w, wpf,  12, 12,  96, tp);
        bias_kernel<<<(2*3*64*64+255)/256, 256>>>(btab);
    }

    // ---- block 0 (shift 0) ----
    attn_kernel<<<NWIN, 512, ASMEM>>>(x, scratch,
        wqkvf, qkv_b, wpf, proj_b, biasm, ln1g, ln1b, 0);
    mlp_kernel<<<TOKENS/64, 512, MSMEM>>>(scratch,
        ln2g, ln2b, w1f, b1, w2f, b2);

    // ---- block 1 (shift 2) ----
    attn_kernel<<<NWIN, 512, ASMEM>>>(scratch, out,
        wqkvf + 12*36*32, qkv_b + 288, wpf + 12*12*32, proj_b + 96,
        biasm + 3*64*64, ln1g + 96, ln1b + 96, 2);
    mlp_kernel<<<TOKENS/64, 512, MSMEM>>>(out,
        ln2g + 96, ln2b + 96, w1f + 12*48*32, b1 + 384, w2f + 48*12*32, b2 + 96);
}